// round 10
// baseline (speedup 1.0000x reference)
#include <cuda_runtime.h>

// QConv2d: new_rho[b] = U2 @ rho[b] @ U2^T, U2 = uc[:,2:4] ⊗ ux ⊗ uy
// R7 half-pipeline structure + packed f32x2 FMA transforms.
//
// smem tile A: 128 rows x 132 words. Half H (threads H*128..+127), named bar:
//   P1h: load rho rows [H*64,+64) coalesced float4 -> A
//   barH
//   P2h: per-thread row-half register transform (packed f32x2)
//   barH
//   P3h: per-thread column x cl=H register transform (in-place)
// __syncthreads
//   P4 : fused uc both sides (packed) + coalesced float4 stores.
//
// U is pre-duplicated in smem as u64 {U,U} pairs -> no dup movs in FMA chains.

#define NT 256
#define RS 132
#define A_WORDS (128 * RS)            // 16896 floats
#define SMEM_WORDS (A_WORDS + 2 * 264)  // per half: 128 u64 Ud + 8 floats wc (264 fl)
#define SMEM_BYTES (SMEM_WORDS * 4)

typedef unsigned long long u64;

__device__ __forceinline__ u64 f2pack(float lo, float hi) {
    u64 r; asm("mov.b64 %0, {%1, %2};" : "=l"(r) : "f"(lo), "f"(hi)); return r;
}
__device__ __forceinline__ void f2unpack(u64 v, float& lo, float& hi) {
    asm("mov.b64 {%0, %1}, %2;" : "=f"(lo), "=f"(hi) : "l"(v));
}
__device__ __forceinline__ u64 f2fma(u64 a, u64 b, u64 c) {
    u64 r; asm("fma.rn.f32x2 %0, %1, %2, %3;" : "=l"(r) : "l"(a), "l"(b), "l"(c));
    return r;
}
__device__ __forceinline__ u64 f2mul(u64 a, u64 b) {
    u64 r; asm("mul.rn.f32x2 %0, %1, %2;" : "=l"(r) : "l"(a), "l"(b)); return r;
}

__device__ __forceinline__ void half_bar(int H) {
    asm volatile("bar.sync %0, 128;" :: "r"(H + 1) : "memory");
}

// In-place 8x8(x) ⊗ 8x8(y) transform of 64 floats, packed f32x2.
// Uyd/Uxd: smem u64 tables, Ud[o*8+k] = {U[o][k], U[o][k]}.
__device__ __forceinline__ void transform64p(float* __restrict__ d,
                                             const u64* __restrict__ Uyd,
                                             const u64* __restrict__ Uxd)
{
    // pass 1: contract over y; packed over x-pairs
#pragma unroll
    for (int xp = 0; xp < 4; xp++) {
        u64 v[8];
#pragma unroll
        for (int k = 0; k < 8; k++)
            v[k] = f2pack(d[(2 * xp) * 8 + k], d[(2 * xp + 1) * 8 + k]);
#pragma unroll
        for (int yo = 0; yo < 8; yo++) {
            u64 acc = f2mul(Uyd[yo * 8], v[0]);
#pragma unroll
            for (int k = 1; k < 8; k++) acc = f2fma(Uyd[yo * 8 + k], v[k], acc);
            f2unpack(acc, d[(2 * xp) * 8 + yo], d[(2 * xp + 1) * 8 + yo]);
        }
    }
    // pass 2: contract over x; packed over adjacent y-pairs (pack is reg-pair free)
#pragma unroll
    for (int yp = 0; yp < 4; yp++) {
        u64 v[8];
#pragma unroll
        for (int k = 0; k < 8; k++)
            v[k] = f2pack(d[k * 8 + 2 * yp], d[k * 8 + 2 * yp + 1]);
#pragma unroll
        for (int xo = 0; xo < 8; xo++) {
            u64 acc = f2mul(Uxd[xo * 8], v[0]);
#pragma unroll
            for (int k = 1; k < 8; k++) acc = f2fma(Uxd[xo * 8 + k], v[k], acc);
            f2unpack(acc, d[xo * 8 + 2 * yp], d[xo * 8 + 2 * yp + 1]);
        }
    }
}

__global__ __launch_bounds__(NT, 2)
void qconv_kernel(const float* __restrict__ rho,
                  const float* __restrict__ gux,
                  const float* __restrict__ guy,
                  const float* __restrict__ guc,
                  float* __restrict__ out)
{
    extern __shared__ float sm[];
    float* A = sm;                              // 128 x 132

    const int tid   = threadIdx.x;
    const int H     = tid >> 7;                 // half id = left-channel block
    const int local = tid & 127;
    // per-half tables: 128 u64 Ud (uy at [0:64), ux at [64:128)) + 8 floats wc
    u64*   sUd = (u64*)(sm + A_WORDS) + H * 132;
    float* swc = (float*)(sUd + 128);

    const int b = blockIdx.x;

    // ---- init duplicated U + wc (inside half barrier domain) ----
    {
        const float uval = (local < 64) ? guy[local] : gux[local - 64];
        sUd[local] = f2pack(uval, uval);
        if (local < 8)                           // i = c'*2 + c
            swc[local] = guc[(local >> 1) * 4 + (local & 1) + 2];
    }

    // ---- P1 (half): load rho rows [H*64,+64) coalesced ----
    {
        const float4* src = (const float4*)(rho + (long)b * 16384) + H * 2048;
#pragma unroll
        for (int i = 0; i < 16; i++) {
            const int idx = local + i * 128;     // float4 index within half
            const float4 v = src[idx];
            const int w = idx * 4;               // word within half
            const int r = H * 64 + (w >> 7);
            const int c = w & 127;
            *(float4*)(A + r * RS + c) = v;
        }
    }
    half_bar(H);

    const u64* Uyd = sUd;
    const u64* Uxd = sUd + 64;

    // ---- P2 (half): right-side transform, one row-half per thread ----
    {
        const int h = local >> 6;                // right-channel half of the row
        const int r = H * 64 + (local & 63);
        float* base = A + r * RS + h * 64;
        float d[64];
#pragma unroll
        for (int i = 0; i < 16; i++) {
            const float4 v = *(const float4*)(base + 4 * i);
            d[4 * i] = v.x; d[4 * i + 1] = v.y; d[4 * i + 2] = v.z; d[4 * i + 3] = v.w;
        }
        transform64p(d, Uyd, Uxd);
#pragma unroll
        for (int i = 0; i < 16; i++)
            *(float4*)(base + 4 * i) =
                make_float4(d[4 * i], d[4 * i + 1], d[4 * i + 2], d[4 * i + 3]);
    }
    half_bar(H);

    // ---- P3 (half): left-side transform, column x cl=H per thread ----
    // Read-set == write-set per thread; no barrier between load and store.
    {
        float* base = A + (H * 64) * RS + local;
        float d[64];
#pragma unroll
        for (int i = 0; i < 64; i++) d[i] = base[i * RS];   // lanes stride-1
        transform64p(d, Uyd, Uxd);
#pragma unroll
        for (int i = 0; i < 64; i++) base[i * RS] = d[i];
    }
    __syncthreads();

    // ---- P4: fused channel expansion (packed) + coalesced store ----
    u64 wd[8];
    {
        const float* wsrc = (const float*)((u64*)(sm + A_WORDS) + 128); // half-0 copy
#pragma unroll
        for (int i = 0; i < 8; i++) wd[i] = f2pack(wsrc[i], wsrc[i]);
    }

    float4* outb = (float4*)(out + (long)b * 65536);
    const float4* Af = (const float4*)A;        // row stride 33 float4

#pragma unroll
    for (int it = 0; it < 4; it++) {
        const int item = tid + it * NT;
        const int irv = item & 15;              // right pixel / 4
        const int il  = item >> 4;              // left pixel, 0..63

        const float4 m00 = Af[il * 33 + irv];              // cl=0, cr=0
        const float4 m01 = Af[il * 33 + 16 + irv];         // cl=0, cr=1
        const float4 m10 = Af[(64 + il) * 33 + irv];       // cl=1, cr=0
        const float4 m11 = Af[(64 + il) * 33 + 16 + irv];  // cl=1, cr=1

        const u64 m00a = f2pack(m00.x, m00.y), m00b = f2pack(m00.z, m00.w);
        const u64 m01a = f2pack(m01.x, m01.y), m01b = f2pack(m01.z, m01.w);
        const u64 m10a = f2pack(m10.x, m10.y), m10b = f2pack(m10.z, m10.w);
        const u64 m11a = f2pack(m11.x, m11.y), m11b = f2pack(m11.z, m11.w);

#pragma unroll
        for (int cpr = 0; cpr < 4; cpr++) {
            const u64 w0 = wd[cpr * 2], w1 = wd[cpr * 2 + 1];
            const u64 t0a = f2fma(w1, m01a, f2mul(w0, m00a));
            const u64 t0b = f2fma(w1, m01b, f2mul(w0, m00b));
            const u64 t1a = f2fma(w1, m11a, f2mul(w0, m10a));
            const u64 t1b = f2fma(w1, m11b, f2mul(w0, m10b));
#pragma unroll
            for (int cpl = 0; cpl < 4; cpl++) {
                const u64 v0 = wd[cpl * 2], v1 = wd[cpl * 2 + 1];
                const u64 oa = f2fma(v1, t1a, f2mul(v0, t0a));
                const u64 ob = f2fma(v1, t1b, f2mul(v0, t0b));
                float4 o;
                f2unpack(oa, o.x, o.y);
                f2unpack(ob, o.z, o.w);
                outb[(cpl * 64 + il) * 64 + cpr * 16 + irv] = o;
            }
        }
    }
}

extern "C" void kernel_launch(void* const* d_in, const int* in_sizes, int n_in,
                              void* d_out, int out_size)
{
    const float* rho = (const float*)d_in[0];
    const float* ux  = (const float*)d_in[1];
    const float* uy  = (const float*)d_in[2];
    const float* uc  = (const float*)d_in[3];
    float* out = (float*)d_out;

    const int B = in_sizes[0] / 16384;

    cudaFuncSetAttribute(qconv_kernel,
                         cudaFuncAttributeMaxDynamicSharedMemorySize, SMEM_BYTES);
    qconv_kernel<<<B, NT, SMEM_BYTES>>>(rho, ux, uy, uc, out);
}

// round 11
// speedup vs baseline: 1.2140x; 1.2140x over previous
#include <cuda_runtime.h>

// QConv2d: new_rho[b] = U2 @ rho[b] @ U2^T, U2 = uc[:,2:4] ⊗ ux ⊗ uy
// R7 half-pipeline structure + SPILL-SAFE packed f32x2 transforms:
//  - d[64] kept scalar; packed v[8] transient per pair-group
//  - #pragma unroll 1 on the pair-group loops so the u64 U-table is NOT
//    hoisted into registers (R10's spill cause); LDS.64 broadcast per use.
//  - P4 scalar (proven R7 code).

#define NT 256
#define RS 132
#define A_WORDS (128 * RS)              // 16896 floats
#define SMEM_WORDS (A_WORDS + 2 * 264)  // per half: 128 u64 Ud + 8 floats wc
#define SMEM_BYTES (SMEM_WORDS * 4)

typedef unsigned long long u64;

__device__ __forceinline__ u64 f2pack(float lo, float hi) {
    u64 r; asm("mov.b64 %0, {%1, %2};" : "=l"(r) : "f"(lo), "f"(hi)); return r;
}
__device__ __forceinline__ void f2unpack(u64 v, float& lo, float& hi) {
    asm("mov.b64 {%0, %1}, %2;" : "=f"(lo), "=f"(hi) : "l"(v));
}
__device__ __forceinline__ u64 f2fma(u64 a, u64 b, u64 c) {
    u64 r; asm("fma.rn.f32x2 %0, %1, %2, %3;" : "=l"(r) : "l"(a), "l"(b), "l"(c));
    return r;
}
__device__ __forceinline__ u64 f2mul(u64 a, u64 b) {
    u64 r; asm("mul.rn.f32x2 %0, %1, %2;" : "=l"(r) : "l"(a), "l"(b)); return r;
}
__device__ __forceinline__ u64 lds64(const u64* p) {
    u64 r; asm volatile("ld.shared.b64 %0, [%1];" : "=l"(r) : "l"(p)); return r;
}

__device__ __forceinline__ void half_bar(int H) {
    asm volatile("bar.sync %0, 128;" :: "r"(H + 1) : "memory");
}

// In-place 8x8(x) ⊗ 8x8(y) transform of 64 scalar floats, packed f32x2 math.
// Uyd/Uxd: smem u64 tables, Ud[o*8+k] = {U[o][k], U[o][k]}.
__device__ __forceinline__ void transform64pl(float* __restrict__ d,
                                              const u64* __restrict__ Uyd,
                                              const u64* __restrict__ Uxd)
{
    // pass 1: contract over y; packed over x-pairs.
#pragma unroll 1
    for (int xp = 0; xp < 4; xp++) {
        u64 v[8];
#pragma unroll
        for (int k = 0; k < 8; k++)
            v[k] = f2pack(d[(2 * xp) * 8 + k], d[(2 * xp + 1) * 8 + k]);
#pragma unroll
        for (int yo = 0; yo < 8; yo++) {
            u64 acc = f2mul(lds64(Uyd + yo * 8), v[0]);
#pragma unroll
            for (int k = 1; k < 8; k++)
                acc = f2fma(lds64(Uyd + yo * 8 + k), v[k], acc);
            f2unpack(acc, d[(2 * xp) * 8 + yo], d[(2 * xp + 1) * 8 + yo]);
        }
    }
    // pass 2: contract over x; packed over adjacent y-pairs.
#pragma unroll 1
    for (int yp = 0; yp < 4; yp++) {
        u64 v[8];
#pragma unroll
        for (int k = 0; k < 8; k++)
            v[k] = f2pack(d[k * 8 + 2 * yp], d[k * 8 + 2 * yp + 1]);
#pragma unroll
        for (int xo = 0; xo < 8; xo++) {
            u64 acc = f2mul(lds64(Uxd + xo * 8), v[0]);
#pragma unroll
            for (int k = 1; k < 8; k++)
                acc = f2fma(lds64(Uxd + xo * 8 + k), v[k], acc);
            f2unpack(acc, d[xo * 8 + 2 * yp], d[xo * 8 + 2 * yp + 1]);
        }
    }
}

__global__ __launch_bounds__(NT, 2)
void qconv_kernel(const float* __restrict__ rho,
                  const float* __restrict__ gux,
                  const float* __restrict__ guy,
                  const float* __restrict__ guc,
                  float* __restrict__ out)
{
    extern __shared__ float sm[];
    float* A = sm;                              // 128 x 132

    const int tid   = threadIdx.x;
    const int H     = tid >> 7;                 // half id = left-channel block
    const int local = tid & 127;
    // per-half tables: 128 u64 Ud (uy [0:64), ux [64:128)) + 8 floats wc
    u64*   sUd = (u64*)(sm + A_WORDS) + H * 132;
    float* swc = (float*)(sUd + 128);

    const int b = blockIdx.x;

    // ---- init duplicated U + wc (inside half barrier domain) ----
    {
        const float uval = (local < 64) ? guy[local] : gux[local - 64];
        sUd[local] = f2pack(uval, uval);
        if (local < 8)                           // i = c'*2 + c
            swc[local] = guc[(local >> 1) * 4 + (local & 1) + 2];
    }

    // ---- P1 (half): load rho rows [H*64,+64) coalesced ----
    {
        const float4* src = (const float4*)(rho + (long)b * 16384) + H * 2048;
#pragma unroll
        for (int i = 0; i < 16; i++) {
            const int idx = local + i * 128;     // float4 index within half
            const float4 v = src[idx];
            const int w = idx * 4;
            const int r = H * 64 + (w >> 7);
            const int c = w & 127;
            *(float4*)(A + r * RS + c) = v;
        }
    }
    half_bar(H);

    const u64* Uyd = sUd;
    const u64* Uxd = sUd + 64;

    // ---- P2 (half): right-side transform, one row-half per thread ----
    {
        const int h = local >> 6;
        const int r = H * 64 + (local & 63);
        float* base = A + r * RS + h * 64;
        float d[64];
#pragma unroll
        for (int i = 0; i < 16; i++) {
            const float4 v = *(const float4*)(base + 4 * i);
            d[4 * i] = v.x; d[4 * i + 1] = v.y; d[4 * i + 2] = v.z; d[4 * i + 3] = v.w;
        }
        transform64pl(d, Uyd, Uxd);
#pragma unroll
        for (int i = 0; i < 16; i++)
            *(float4*)(base + 4 * i) =
                make_float4(d[4 * i], d[4 * i + 1], d[4 * i + 2], d[4 * i + 3]);
    }
    half_bar(H);

    // ---- P3 (half): left-side transform, column x cl=H per thread ----
    {
        float* base = A + (H * 64) * RS + local;
        float d[64];
#pragma unroll
        for (int i = 0; i < 64; i++) d[i] = base[i * RS];   // lanes stride-1
        transform64pl(d, Uyd, Uxd);
#pragma unroll
        for (int i = 0; i < 64; i++) base[i * RS] = d[i];
    }
    __syncthreads();

    // ---- P4: fused channel expansion (scalar, proven) + coalesced store ----
    float wc[8];
    {
        const float* wsrc = (const float*)((u64*)(sm + A_WORDS) + 128); // half-0
#pragma unroll
        for (int i = 0; i < 8; i++) wc[i] = wsrc[i];
    }

    float4* outb = (float4*)(out + (long)b * 65536);
    const float4* Af = (const float4*)A;        // row stride 33 float4

#pragma unroll
    for (int it = 0; it < 4; it++) {
        const int item = tid + it * NT;
        const int irv = item & 15;              // right pixel / 4
        const int il  = item >> 4;              // left pixel, 0..63

        const float4 m00 = Af[il * 33 + irv];              // cl=0, cr=0
        const float4 m01 = Af[il * 33 + 16 + irv];         // cl=0, cr=1
        const float4 m10 = Af[(64 + il) * 33 + irv];       // cl=1, cr=0
        const float4 m11 = Af[(64 + il) * 33 + 16 + irv];  // cl=1, cr=1

#pragma unroll
        for (int cpr = 0; cpr < 4; cpr++) {
            const float w0 = wc[cpr * 2], w1 = wc[cpr * 2 + 1];
            float4 t0, t1;
            t0.x = fmaf(w1, m01.x, w0 * m00.x);
            t0.y = fmaf(w1, m01.y, w0 * m00.y);
            t0.z = fmaf(w1, m01.z, w0 * m00.z);
            t0.w = fmaf(w1, m01.w, w0 * m00.w);
            t1.x = fmaf(w1, m11.x, w0 * m10.x);
            t1.y = fmaf(w1, m11.y, w0 * m10.y);
            t1.z = fmaf(w1, m11.z, w0 * m10.z);
            t1.w = fmaf(w1, m11.w, w0 * m10.w);
#pragma unroll
            for (int cpl = 0; cpl < 4; cpl++) {
                const float v0 = wc[cpl * 2], v1 = wc[cpl * 2 + 1];
                float4 o;
                o.x = fmaf(v1, t1.x, v0 * t0.x);
                o.y = fmaf(v1, t1.y, v0 * t0.y);
                o.z = fmaf(v1, t1.z, v0 * t0.z);
                o.w = fmaf(v1, t1.w, v0 * t0.w);
                outb[(cpl * 64 + il) * 64 + cpr * 16 + irv] = o;
            }
        }
    }
}

extern "C" void kernel_launch(void* const* d_in, const int* in_sizes, int n_in,
                              void* d_out, int out_size)
{
    const float* rho = (const float*)d_in[0];
    const float* ux  = (const float*)d_in[1];
    const float* uy  = (const float*)d_in[2];
    const float* uc  = (const float*)d_in[3];
    float* out = (float*)d_out;

    const int B = in_sizes[0] / 16384;

    cudaFuncSetAttribute(qconv_kernel,
                         cudaFuncAttributeMaxDynamicSharedMemorySize, SMEM_BYTES);
    qconv_kernel<<<B, NT, SMEM_BYTES>>>(rho, ux, uy, uc, out);
}

// round 12
// speedup vs baseline: 1.9722x; 1.6245x over previous
#include <cuda_runtime.h>

// QConv2d: new_rho[b] = U2 @ rho[b] @ U2^T, U2 = uc[:,2:4] ⊗ ux ⊗ uy
// R7 half-pipeline structure + persistently-packed f32x2 transforms.
//  - dd[32] u64 = x-pair-packed 64-float vector (64 regs), FULL unroll (static idx)
//  - U via volatile LDS.64 (no CSE/hoist); pass2 uses pre-paired U + lane dups (ALU)
//  - P4 packed (R5-verified epilogue)

#define NT 256
#define RS 132
#define A_WORDS (128 * RS)              // 16896 floats
// per half: Uyd 64 u64 + Uxp 32 u64 + wc 8 floats -> 100 u64 slots (200 floats)
#define SMEM_WORDS (A_WORDS + 2 * 200)
#define SMEM_BYTES (SMEM_WORDS * 4)

typedef unsigned long long u64;

__device__ __forceinline__ u64 f2pack(float lo, float hi) {
    u64 r; asm("mov.b64 %0, {%1, %2};" : "=l"(r) : "f"(lo), "f"(hi)); return r;
}
__device__ __forceinline__ void f2unpack(u64 v, float& lo, float& hi) {
    asm("mov.b64 {%0, %1}, %2;" : "=f"(lo), "=f"(hi) : "l"(v));
}
__device__ __forceinline__ u64 f2fma(u64 a, u64 b, u64 c) {
    u64 r; asm("fma.rn.f32x2 %0, %1, %2, %3;" : "=l"(r) : "l"(a), "l"(b), "l"(c));
    return r;
}
__device__ __forceinline__ u64 f2mul(u64 a, u64 b) {
    u64 r; asm("mul.rn.f32x2 %0, %1, %2;" : "=l"(r) : "l"(a), "l"(b)); return r;
}
// volatile shared load: prevents CSE/hoisting of the U tables into registers
__device__ __forceinline__ u64 vld(const u64* p) {
    return *(volatile const u64*)p;
}

__device__ __forceinline__ void half_bar(int H) {
    asm volatile("bar.sync %0, 128;" :: "r"(H + 1) : "memory");
}

// In-place 8x8(x) ⊗ 8x8(y) transform of a packed 64-vector.
// dd[xp*8+y] = { d[2xp][y], d[2xp+1][y] }  (element d[x][y] = v[x*8+y])
// Uyd[yo*8+y] = {Uy[yo][y], Uy[yo][y]}   (dup)
// Uxp[xop*8+x] = {Ux[2xop][x], Ux[2xop+1][x]}  (pair)
__device__ __forceinline__ void transform_packed(u64* __restrict__ dd,
                                                 const u64* __restrict__ Uyd,
                                                 const u64* __restrict__ Uxp)
{
    // ---- pass 1: contract over y (x-pairs packed natively) ----
#pragma unroll
    for (int g = 0; g < 2; g++) {          // xp groups {0,1}, {2,3}
        u64 acc[16];
#pragma unroll
        for (int yo = 0; yo < 8; yo++) {
            u64 u = vld(Uyd + yo * 8);
            u64 a0 = f2mul(u, dd[(2 * g) * 8]);
            u64 a1 = f2mul(u, dd[(2 * g + 1) * 8]);
#pragma unroll
            for (int y = 1; y < 8; y++) {
                u = vld(Uyd + yo * 8 + y);
                a0 = f2fma(u, dd[(2 * g) * 8 + y], a0);
                a1 = f2fma(u, dd[(2 * g + 1) * 8 + y], a1);
            }
            acc[yo] = a0; acc[8 + yo] = a1;
        }
#pragma unroll
        for (int yo = 0; yo < 8; yo++) {
            dd[(2 * g) * 8 + yo]     = acc[yo];
            dd[(2 * g + 1) * 8 + yo] = acc[8 + yo];
        }
    }
    // ---- pass 2: contract over x (lane-dup inputs, pre-paired U) ----
#pragma unroll
    for (int yb = 0; yb < 4; yb++) {       // y in {2yb, 2yb+1}
        u64 dlo[8], dhi[8];                // [xp*2 + j], j = y offset
#pragma unroll
        for (int xp = 0; xp < 4; xp++) {
#pragma unroll
            for (int j = 0; j < 2; j++) {
                float lo, hi;
                f2unpack(dd[xp * 8 + 2 * yb + j], lo, hi);
                dlo[xp * 2 + j] = f2pack(lo, lo);
                dhi[xp * 2 + j] = f2pack(hi, hi);
            }
        }
#pragma unroll
        for (int xop = 0; xop < 4; xop++) {
            u64 ua = vld(Uxp + xop * 8);
            u64 a0 = f2mul(ua, dlo[0]);
            u64 a1 = f2mul(ua, dlo[1]);
            u64 ub = vld(Uxp + xop * 8 + 1);
            a0 = f2fma(ub, dhi[0], a0);
            a1 = f2fma(ub, dhi[1], a1);
#pragma unroll
            for (int xp = 1; xp < 4; xp++) {
                ua = vld(Uxp + xop * 8 + 2 * xp);
                a0 = f2fma(ua, dlo[xp * 2], a0);
                a1 = f2fma(ua, dlo[xp * 2 + 1], a1);
                ub = vld(Uxp + xop * 8 + 2 * xp + 1);
                a0 = f2fma(ub, dhi[xp * 2], a0);
                a1 = f2fma(ub, dhi[xp * 2 + 1], a1);
            }
            dd[xop * 8 + 2 * yb]     = a0;   // inputs already in dlo/dhi
            dd[xop * 8 + 2 * yb + 1] = a1;
        }
    }
}

__global__ __launch_bounds__(NT, 2)
void qconv_kernel(const float* __restrict__ rho,
                  const float* __restrict__ gux,
                  const float* __restrict__ guy,
                  const float* __restrict__ guc,
                  float* __restrict__ out)
{
    extern __shared__ float sm[];
    float* A = sm;                               // 128 x 132

    const int tid   = threadIdx.x;
    const int H     = tid >> 7;                  // half = left-channel block
    const int local = tid & 127;
    u64*   tab = (u64*)(sm + A_WORDS) + H * 100; // per-half tables
    u64*   Uyd = tab;                            // 64 dup entries
    u64*   Uxp = tab + 64;                       // 32 pair entries
    float* swc = (float*)(tab + 96);             // 8 floats

    const int b = blockIdx.x;

    // ---- init tables (inside half barrier domain) ----
    if (local < 64) {
        const float v = guy[local];
        Uyd[local] = f2pack(v, v);
    } else if (local < 96) {
        const int i = local - 64;                // i = xop*8 + x
        const int xop = i >> 3, x = i & 7;
        Uxp[i] = f2pack(gux[(2 * xop) * 8 + x], gux[(2 * xop + 1) * 8 + x]);
    } else if (local < 104) {
        const int i = local - 96;                // i = c'*2 + c
        swc[i] = guc[(i >> 1) * 4 + (i & 1) + 2];
    }

    // ---- P1 (half): load rho rows [H*64,+64) coalesced ----
    {
        const float4* src = (const float4*)(rho + (long)b * 16384) + H * 2048;
#pragma unroll
        for (int i = 0; i < 16; i++) {
            const int idx = local + i * 128;
            const float4 v = src[idx];
            const int w = idx * 4;
            const int r = H * 64 + (w >> 7);
            const int c = w & 127;
            *(float4*)(A + r * RS + c) = v;
        }
    }
    half_bar(H);

    // ---- P2 (half): right-side transform, one row-half per thread ----
    {
        const int h = local >> 6;
        const int r = H * 64 + (local & 63);
        float* base = A + r * RS + h * 64;
        u64 dd[32];
#pragma unroll
        for (int xp = 0; xp < 4; xp++) {
#pragma unroll
            for (int yq = 0; yq < 2; yq++) {
                const float4 va = *(const float4*)(base + (4 * xp + yq) * 4);
                const float4 vb = *(const float4*)(base + (4 * xp + 2 + yq) * 4);
                dd[xp * 8 + yq * 4 + 0] = f2pack(va.x, vb.x);
                dd[xp * 8 + yq * 4 + 1] = f2pack(va.y, vb.y);
                dd[xp * 8 + yq * 4 + 2] = f2pack(va.z, vb.z);
                dd[xp * 8 + yq * 4 + 3] = f2pack(va.w, vb.w);
            }
        }
        transform_packed(dd, Uyd, Uxp);
#pragma unroll
        for (int xp = 0; xp < 4; xp++) {
#pragma unroll
            for (int yq = 0; yq < 2; yq++) {
                float4 va, vb;
                f2unpack(dd[xp * 8 + yq * 4 + 0], va.x, vb.x);
                f2unpack(dd[xp * 8 + yq * 4 + 1], va.y, vb.y);
                f2unpack(dd[xp * 8 + yq * 4 + 2], va.z, vb.z);
                f2unpack(dd[xp * 8 + yq * 4 + 3], va.w, vb.w);
                *(float4*)(base + (4 * xp + yq) * 4)     = va;
                *(float4*)(base + (4 * xp + 2 + yq) * 4) = vb;
            }
        }
    }
    half_bar(H);

    // ---- P3 (half): left-side transform, column x cl=H per thread ----
    {
        float* base = A + (H * 64) * RS + local;
        u64 dd[32];
#pragma unroll
        for (int xp = 0; xp < 4; xp++)
#pragma unroll
            for (int y = 0; y < 8; y++)
                dd[xp * 8 + y] = f2pack(base[(16 * xp + y) * RS],
                                        base[(16 * xp + 8 + y) * RS]);
        transform_packed(dd, Uyd, Uxp);
#pragma unroll
        for (int xp = 0; xp < 4; xp++)
#pragma unroll
            for (int y = 0; y < 8; y++) {
                float lo, hi;
                f2unpack(dd[xp * 8 + y], lo, hi);
                base[(16 * xp + y) * RS]     = lo;
                base[(16 * xp + 8 + y) * RS] = hi;
            }
    }
    __syncthreads();

    // ---- P4: fused channel expansion (packed, R5-verified) + store ----
    u64 wd[8];
    {
        const float* wsrc = (const float*)((u64*)(sm + A_WORDS) + 96); // half-0 wc
#pragma unroll
        for (int i = 0; i < 8; i++) wd[i] = f2pack(wsrc[i], wsrc[i]);
    }

    float4* outb = (float4*)(out + (long)b * 65536);
    const float4* Af = (const float4*)A;         // row stride 33 float4

#pragma unroll
    for (int it = 0; it < 4; it++) {
        const int item = tid + it * NT;
        const int irv = item & 15;
        const int il  = item >> 4;

        const float4 m00 = Af[il * 33 + irv];
        const float4 m01 = Af[il * 33 + 16 + irv];
        const float4 m10 = Af[(64 + il) * 33 + irv];
        const float4 m11 = Af[(64 + il) * 33 + 16 + irv];

        const u64 m00a = f2pack(m00.x, m00.y), m00b = f2pack(m00.z, m00.w);
        const u64 m01a = f2pack(m01.x, m01.y), m01b = f2pack(m01.z, m01.w);
        const u64 m10a = f2pack(m10.x, m10.y), m10b = f2pack(m10.z, m10.w);
        const u64 m11a = f2pack(m11.x, m11.y), m11b = f2pack(m11.z, m11.w);

#pragma unroll
        for (int cpr = 0; cpr < 4; cpr++) {
            const u64 w0 = wd[cpr * 2], w1 = wd[cpr * 2 + 1];
            const u64 t0a = f2fma(w1, m01a, f2mul(w0, m00a));
            const u64 t0b = f2fma(w1, m01b, f2mul(w0, m00b));
            const u64 t1a = f2fma(w1, m11a, f2mul(w0, m10a));
            const u64 t1b = f2fma(w1, m11b, f2mul(w0, m10b));
#pragma unroll
            for (int cpl = 0; cpl < 4; cpl++) {
                const u64 v0 = wd[cpl * 2], v1 = wd[cpl * 2 + 1];
                const u64 oa = f2fma(v1, t1a, f2mul(v0, t0a));
                const u64 ob = f2fma(v1, t1b, f2mul(v0, t0b));
                float4 o;
                f2unpack(oa, o.x, o.y);
                f2unpack(ob, o.z, o.w);
                outb[(cpl * 64 + il) * 64 + cpr * 16 + irv] = o;
            }
        }
    }
}

extern "C" void kernel_launch(void* const* d_in, const int* in_sizes, int n_in,
                              void* d_out, int out_size)
{
    const float* rho = (const float*)d_in[0];
    const float* ux  = (const float*)d_in[1];
    const float* uy  = (const float*)d_in[2];
    const float* uc  = (const float*)d_in[3];
    float* out = (float*)d_out;

    const int B = in_sizes[0] / 16384;

    cudaFuncSetAttribute(qconv_kernel,
                         cudaFuncAttributeMaxDynamicSharedMemorySize, SMEM_BYTES);
    qconv_kernel<<<B, NT, SMEM_BYTES>>>(rho, ux, uy, uc, out);
}

// round 15
// speedup vs baseline: 2.1355x; 1.0828x over previous
#include <cuda_runtime.h>

// QConv2d: new_rho[b] = U2 @ rho[b] @ U2^T, U2 = uc[:,2:4] ⊗ ux ⊗ uy
// R7 half-pipeline structure (best measured) + serial-tail cuts:
//  - P1 prefetches all 16 LDG.128 into registers BEFORE table init, then STS
//  - __ldg for rho, __stcs (streaming) for the write-once output
//
// smem tile A: 128 rows x 132 words. Half H (threads H*128..+127), named bar:
//   P1h: prefetch regs -> STS rows [H*64,+64)
//   barH
//   P2h: per-thread row-half register transform (scalar FMA)
//   barH
//   P3h: per-thread column x cl=H register transform (in-place)
// __syncthreads
//   P4 : fused uc both sides + coalesced streaming float4 stores.

#define NT 256
#define RS 132
#define A_WORDS (128 * RS)            // 16896
#define SMEM_WORDS (A_WORDS + 2 * 136)
#define SMEM_BYTES (SMEM_WORDS * 4)

__device__ __forceinline__ void half_bar(int H) {
    asm volatile("bar.sync %0, 128;" :: "r"(H + 1) : "memory");
}

__device__ __forceinline__ void transform64(float* __restrict__ d,
                                            const float4* __restrict__ Uy4,
                                            const float4* __restrict__ Ux4)
{
    // uy pass: 8 contiguous groups (x fixed)
#pragma unroll
    for (int x = 0; x < 8; x++) {
        float v[8];
#pragma unroll
        for (int k = 0; k < 8; k++) v[k] = d[x * 8 + k];
#pragma unroll
        for (int yo = 0; yo < 8; yo++) {
            const float4 ua = Uy4[yo * 2], ub = Uy4[yo * 2 + 1];
            float a =      ua.x * v[0];
            a = fmaf(ua.y, v[1], a);
            a = fmaf(ua.z, v[2], a);
            a = fmaf(ua.w, v[3], a);
            a = fmaf(ub.x, v[4], a);
            a = fmaf(ub.y, v[5], a);
            a = fmaf(ub.z, v[6], a);
            a = fmaf(ub.w, v[7], a);
            d[x * 8 + yo] = a;
        }
    }
    // ux pass: stride-8 groups (y fixed)
#pragma unroll
    for (int y = 0; y < 8; y++) {
        float v[8];
#pragma unroll
        for (int k = 0; k < 8; k++) v[k] = d[k * 8 + y];
#pragma unroll
        for (int xo = 0; xo < 8; xo++) {
            const float4 ua = Ux4[xo * 2], ub = Ux4[xo * 2 + 1];
            float a =      ua.x * v[0];
            a = fmaf(ua.y, v[1], a);
            a = fmaf(ua.z, v[2], a);
            a = fmaf(ua.w, v[3], a);
            a = fmaf(ub.x, v[4], a);
            a = fmaf(ub.y, v[5], a);
            a = fmaf(ub.z, v[6], a);
            a = fmaf(ub.w, v[7], a);
            d[xo * 8 + y] = a;
        }
    }
}

__global__ __launch_bounds__(NT, 2)
void qconv_kernel(const float* __restrict__ rho,
                  const float* __restrict__ gux,
                  const float* __restrict__ guy,
                  const float* __restrict__ guc,
                  float* __restrict__ out)
{
    extern __shared__ float sm[];
    float* A = sm;                        // 128 x 132

    const int tid   = threadIdx.x;
    const int H     = tid >> 7;           // half id = left-channel block
    const int local = tid & 127;
    float* sU = sm + A_WORDS + H * 136;   // per-half: [0:64) uy, [64:128) ux, [128:136) wc

    const int b = blockIdx.x;

    // ---- P1 prefetch: issue all 16 LDG.128 first (MLP=16) ----
    float4 pf[16];
    {
        const float4* src = (const float4*)(rho + (long)b * 16384) + H * 2048;
#pragma unroll
        for (int i = 0; i < 16; i++)
            pf[i] = __ldg(src + local + i * 128);
    }

    // ---- U-table init overlaps the inflight loads ----
    if (local < 64) {
        sU[local] = __ldg(guy + local);
    } else {
        sU[local] = __ldg(gux + local - 64);
    }
    if (local < 8)                         // i = c'*2 + c
        sU[128 + local] = __ldg(guc + (local >> 1) * 4 + (local & 1) + 2);

    // ---- P1 store phase ----
    {
#pragma unroll
        for (int i = 0; i < 16; i++) {
            const int idx = local + i * 128;  // float4 index within half
            const int w = idx * 4;
            const int r = H * 64 + (w >> 7);
            const int c = w & 127;
            *(float4*)(A + r * RS + c) = pf[i];
        }
    }
    half_bar(H);

    const float4* Uy4 = (const float4*)sU;
    const float4* Ux4 = (const float4*)(sU + 64);

    // ---- P2 (half): right-side transform, one row-half per thread ----
    {
        const int h = local >> 6;             // right-channel half of the row
        const int r = H * 64 + (local & 63);
        float* base = A + r * RS + h * 64;
        float d[64];
#pragma unroll
        for (int i = 0; i < 16; i++) {
            const float4 v = *(const float4*)(base + 4 * i);
            d[4 * i] = v.x; d[4 * i + 1] = v.y; d[4 * i + 2] = v.z; d[4 * i + 3] = v.w;
        }
        transform64(d, Uy4, Ux4);
#pragma unroll
        for (int i = 0; i < 16; i++)
            *(float4*)(base + 4 * i) =
                make_float4(d[4 * i], d[4 * i + 1], d[4 * i + 2], d[4 * i + 3]);
    }
    half_bar(H);

    // ---- P3 (half): left-side transform, column x cl=H per thread ----
    // Read-set == write-set per thread; no barrier between load and store.
    {
        float* base = A + (H * 64) * RS + local;
        float d[64];
#pragma unroll
        for (int i = 0; i < 64; i++) d[i] = base[i * RS];   // lanes stride-1
        transform64(d, Uy4, Ux4);
#pragma unroll
        for (int i = 0; i < 64; i++) base[i * RS] = d[i];
    }
    __syncthreads();

    // ---- P4: fused channel expansion on both sides + streaming stores ----
    float wc[8];
    {
        const float* wsrc = sm + A_WORDS + 128;   // half-0 copy (post-sync)
#pragma unroll
        for (int i = 0; i < 8; i++) wc[i] = wsrc[i];
    }

    float4* outb = (float4*)(out + (long)b * 65536);
    const float4* Af = (const float4*)A;          // row stride 33 float4

#pragma unroll
    for (int it = 0; it < 4; it++) {
        const int item = tid + it * NT;
        const int irv = item & 15;                // right pixel / 4
        const int il  = item >> 4;                // left pixel, 0..63

        const float4 m00 = Af[il * 33 + irv];              // cl=0, cr=0
        const float4 m01 = Af[il * 33 + 16 + irv];         // cl=0, cr=1
        const float4 m10 = Af[(64 + il) * 33 + irv];       // cl=1, cr=0
        const float4 m11 = Af[(64 + il) * 33 + 16 + irv];  // cl=1, cr=1

#pragma unroll
        for (int cpr = 0; cpr < 4; cpr++) {
            const float w0 = wc[cpr * 2], w1 = wc[cpr * 2 + 1];
            float4 t0, t1;
            t0.x = fmaf(w1, m01.x, w0 * m00.x);
            t0.y = fmaf(w1, m01.y, w0 * m00.y);
            t0.z = fmaf(w1, m01.z, w0 * m00.z);
            t0.w = fmaf(w1, m01.w, w0 * m00.w);
            t1.x = fmaf(w1, m11.x, w0 * m10.x);
            t1.y = fmaf(w1, m11.y, w0 * m10.y);
            t1.z = fmaf(w1, m11.z, w0 * m10.z);
            t1.w = fmaf(w1, m11.w, w0 * m10.w);
#pragma unroll
            for (int cpl = 0; cpl < 4; cpl++) {
                const float v0 = wc[cpl * 2], v1 = wc[cpl * 2 + 1];
                float4 o;
                o.x = fmaf(v1, t1.x, v0 * t0.x);
                o.y = fmaf(v1, t1.y, v0 * t0.y);
                o.z = fmaf(v1, t1.z, v0 * t0.z);
                o.w = fmaf(v1, t1.w, v0 * t0.w);
                __stcs(outb + (cpl * 64 + il) * 64 + cpr * 16 + irv, o);
            }
        }
    }
}

extern "C" void kernel_launch(void* const* d_in, const int* in_sizes, int n_in,
                              void* d_out, int out_size)
{
    const float* rho = (const float*)d_in[0];
    const float* ux  = (const float*)d_in[1];
    const float* uy  = (const float*)d_in[2];
    const float* uc  = (const float*)d_in[3];
    float* out = (float*)d_out;

    const int B = in_sizes[0] / 16384;

    cudaFuncSetAttribute(qconv_kernel,
                         cudaFuncAttributeMaxDynamicSharedMemorySize, SMEM_BYTES);
    qconv_kernel<<<B, NT, SMEM_BYTES>>>(rho, ux, uy, uc, out);
}